// round 13
// baseline (speedup 1.0000x reference)
#include <cuda_runtime.h>
#include <cuda_fp16.h>
#include <cstdint>

// ---------------------------------------------------------------------------
// CapsuleNetwork forward, GB300 sm_103a — baseline-PTX tensor cores.
// Plain fp16 GEMM, x64 operand scaling (power-of-2, exact).
// R13: caps_gemm split along batch: CTA tile 128x64, grid 288, 256 thr,
//      2 CTAs/SM — independent CTAs overlap each other's barrier bubbles.
//
// Launches:
//  1. repack_w1 : conv1_w (c,81) -> w1t (81,256)
//  2. wsplit    : pc_w (n,c,81) -> 64*W fp16 [81][outch][c]  (smem-staged)
//  3. conv1     : x -> relu -> 64*h fp16 [pos][b][c]  (fused transpose)
//  4. caps_gemm : mma.sync 128x64, K=64/stage, fused bias+squash -> u
//  5. uhat      : u x W_digit -> u_hat fp16 (B,1152,160)
//  6. routing   : 3 routing iters fused per image -> v
// ---------------------------------------------------------------------------

#define NB    256
#define HW1   400
#define NPRI  1152
#define JO    160

// ------------------------------- scratch -----------------------------------
__device__ float g_w1t[81 * 256];
__device__ __half g_hh[(size_t)400 * 256 * 256];           // 52.4 MB [pos][b][c]
__device__ __half g_wh[(size_t)81 * 256 * 256];            // 10.6 MB [k][n][c]
__device__ float g_u  [(size_t)NPRI * 256 * 8];            // 9.4 MB  [i][b][d]
__device__ __half g_uhat[(size_t)NB * NPRI * JO];          // 94.4 MB

// ------------------------------ ptx helpers --------------------------------
__device__ __forceinline__ uint32_t smem_u32(const void* p) {
    uint32_t a;
    asm("{ .reg .u64 t; cvta.to.shared.u64 t, %1; cvt.u32.u64 %0, t; }"
        : "=r"(a) : "l"(p));
    return a;
}
__device__ __forceinline__ void cpasync16(uint32_t s, const void* g) {
    asm volatile("cp.async.cg.shared.global [%0], [%1], 16;" :: "r"(s), "l"(g));
}
__device__ __forceinline__ void cp_commit() {
    asm volatile("cp.async.commit_group;" ::: "memory");
}
template<int N> __device__ __forceinline__ void cp_wait() {
    asm volatile("cp.async.wait_group %0;" :: "n"(N) : "memory");
}
__device__ __forceinline__ void ldm4(uint32_t* r, uint32_t a) {
    asm volatile("ldmatrix.sync.aligned.m8n8.x4.shared.b16 {%0,%1,%2,%3}, [%4];"
                 : "=r"(r[0]), "=r"(r[1]), "=r"(r[2]), "=r"(r[3]) : "r"(a));
}
__device__ __forceinline__ void mma16816(float* c, const uint32_t* a,
                                         const uint32_t* b) {
    asm volatile(
        "mma.sync.aligned.m16n8k16.row.col.f32.f16.f16.f32 "
        "{%0,%1,%2,%3}, {%4,%5,%6,%7}, {%8,%9}, {%0,%1,%2,%3};"
        : "+f"(c[0]), "+f"(c[1]), "+f"(c[2]), "+f"(c[3])
        : "r"(a[0]), "r"(a[1]), "r"(a[2]), "r"(a[3]), "r"(b[0]), "r"(b[1]));
}

// ------------------------------ f32x2 helpers ------------------------------
__device__ __forceinline__ unsigned long long pk2(float lo, float hi) {
    unsigned long long r;
    asm("mov.b64 %0, {%1, %2};" : "=l"(r) : "f"(lo), "f"(hi));
    return r;
}
__device__ __forceinline__ void upk2(unsigned long long v, float& lo, float& hi) {
    asm("mov.b64 {%0, %1}, %2;" : "=f"(lo), "=f"(hi) : "l"(v));
}
__device__ __forceinline__ void fma2(unsigned long long& d,
                                     unsigned long long a, unsigned long long b) {
    asm("fma.rn.f32x2 %0, %1, %2, %0;" : "+l"(d) : "l"(a), "l"(b));
}

// ------------------------------ repacks ------------------------------------
__global__ void repack_w1_kernel(const float* __restrict__ w) {
    int k = blockIdx.x, c = threadIdx.x;
    g_w1t[k * 256 + c] = w[c * 81 + k];
}

// block = one outch n; smem-staged coalesced load, conflict-free stride-81 read.
__global__ void wsplit_kernel(const float* __restrict__ w) {
    extern __shared__ float wsm[];          // 20736 floats
    int n = blockIdx.x, tid = threadIdx.x;
    const float* src = w + (size_t)n * 20736;
    for (int e = tid; e < 20736; e += 256) wsm[e] = src[e] * 64.f;
    __syncthreads();
    int c = tid;
    for (int k = 0; k < 81; k++) {
        g_wh[((size_t)k * 256 + n) * 256 + c] = __float2half_rn(wsm[c * 81 + k]);
    }
}

// ------------------------------ conv1 (fused fp16 out, NP=5) ---------------
__device__ __forceinline__ void conv1_tile5(const float* __restrict__ ws,
                                            const float* __restrict__ xs,
                                            const float* __restrict__ bias,
                                            int b, int h0, int tx, int ty, int chunk) {
    const int NP = 5;
    int idx[NP], posA[NP];
    #pragma unroll
    for (int p = 0; p < NP; p++) {
        int pos = ty + 16 * (chunk * NP + p);
        posA[p] = pos;
        idx[p] = (pos / 20) * 28 + (pos % 20);
    }
    unsigned long long acc[NP][4];
    #pragma unroll
    for (int p = 0; p < NP; p++)
        #pragma unroll
        for (int q = 0; q < 4; q++) acc[p][q] = 0ull;

    for (int ky = 0; ky < 9; ky++) {
        for (int kx = 0; kx < 9; kx++) {
            int k = ky * 9 + kx;
            float4 wa = ((const float4*)ws)[k * 32 + tx];
            float4 wb = ((const float4*)ws)[k * 32 + 16 + tx];
            unsigned long long w0 = pk2(wa.x, wa.y), w1 = pk2(wa.z, wa.w);
            unsigned long long w2 = pk2(wb.x, wb.y), w3 = pk2(wb.z, wb.w);
            int off = ky * 28 + kx;
            #pragma unroll
            for (int p = 0; p < NP; p++) {
                float xv = xs[idx[p] + off];
                unsigned long long xx = pk2(xv, xv);
                fma2(acc[p][0], w0, xx);
                fma2(acc[p][1], w1, xx);
                fma2(acc[p][2], w2, xx);
                fma2(acc[p][3], w3, xx);
            }
        }
    }
    // store: relu, x64, fp16, layout [pos][b][c]
    #pragma unroll
    for (int p = 0; p < NP; p++) {
        int pos = posA[p];
        #pragma unroll
        for (int q = 0; q < 4; q++) {
            float lo, hi; upk2(acc[p][q], lo, hi);
            int ch = (q < 2) ? (h0 + tx * 4 + 2 * q) : (h0 + 64 + tx * 4 + 2 * (q - 2));
            int bi = 2 * q;
            float v0 = fmaxf(lo + bias[bi], 0.f) * 64.f;
            float v1 = fmaxf(hi + bias[bi + 1], 0.f) * 64.f;
            size_t o = ((size_t)pos * 256 + b) * 256 + ch;
            *(__half2*)(g_hh + o) = __floats2half2_rn(v0, v1);
        }
    }
}

__global__ __launch_bounds__(256, 2)
void conv1_kernel(const float* __restrict__ x, const float* __restrict__ b1) {
    __shared__ float ws[81 * 128];
    __shared__ float xs[784];
    int bx = blockIdx.x;
    int b  = bx >> 1;
    int h0 = (bx & 1) << 7;
    int tid = threadIdx.x;
    {
        float4* wd = (float4*)ws;
        for (int e = tid; e < 81 * 32; e += 256) {
            int k = e >> 5, v = e & 31;
            wd[e] = ((const float4*)g_w1t)[k * 64 + (h0 >> 2) + v];
        }
        float4* xd = (float4*)xs;
        const float4* xsrc = (const float4*)(x + b * 784);
        for (int e = tid; e < 196; e += 256) xd[e] = xsrc[e];
    }
    __syncthreads();
    int tx = tid & 15, ty = tid >> 4;
    float bias[8];
    #pragma unroll
    for (int cc = 0; cc < 4; cc++) {
        bias[cc]     = b1[h0 + tx * 4 + cc];
        bias[4 + cc] = b1[h0 + 64 + tx * 4 + cc];
    }
    #pragma unroll
    for (int chunk = 0; chunk < 5; chunk++)
        conv1_tile5(ws, xs, bias, b, h0, tx, ty, chunk);
}

// ------------------------------ caps_gemm ----------------------------------
// grid 288 = 36 pos x 2 mt x 4 nt.  CTA tile M128(outch) x N64(batch).
// K=64/stage, 324 stages, 4-deep 24KB ring (96KB/CTA, 2 CTAs/SM).
// 256 threads, 8 warps 4(M)x2(N), warp tile 32x32, fragment double-buffer.
// Epilogue: bias + squash fused via shfl butterfly over d-lanes -> g_u.
__device__ __forceinline__ uint32_t swz8(int row, int u) {
    return (uint32_t)(row * 128 + ((u ^ (row & 7)) * 16));
}

// stage slot: A (128 rows x 128B) at +0 (16KB), B (64 rows x 128B) at +16384 (8KB)
__device__ __forceinline__ void load_stage(int s, uint32_t sbase,
                                           int pos, int mt, int nt, int tid) {
    int koff = s >> 2, c0 = (s & 3) << 6;
    int ky = koff / 9, kx = koff - ky * 9;
    int oy = pos / 6, ox = pos % 6;
    int plin = (2 * oy + ky) * 20 + (2 * ox + kx);
    // A: 1024 cpasync16 -> 4 per thread
    {
        int row = tid >> 1;
        int u0 = (tid & 1) * 4;
        size_t aoff = ((size_t)(koff * 256 + mt * 128 + row)) * 256 + c0;
        #pragma unroll
        for (int uu = 0; uu < 4; uu++) {
            int u = u0 + uu;
            cpasync16(sbase + swz8(row, u), g_wh + aoff + u * 8);
        }
    }
    // B: 512 cpasync16 -> 2 per thread
    {
        int row = tid >> 2;
        int u0 = (tid & 3) * 2;
        size_t boff = ((size_t)(plin * 256 + nt * 64 + row)) * 256 + c0;
        #pragma unroll
        for (int uu = 0; uu < 2; uu++) {
            int u = u0 + uu;
            cpasync16(sbase + 16384 + swz8(row, u), g_hh + boff + u * 8);
        }
    }
}

__global__ __launch_bounds__(256, 2)
void caps_gemm_kernel(const float* __restrict__ pcb) {
    extern __shared__ __align__(1024) char smem[];
    uint32_t sb = smem_u32(smem);

    int tid = threadIdx.x, lane = tid & 31, wid = tid >> 5;
    int wm = wid >> 1, wn = wid & 1;
    int bid = blockIdx.x;
    int pos = bid >> 3, mt = (bid >> 2) & 1, nt = bid & 3;

    // per-warp static ldmatrix offsets
    int a_row = wm * 32 + (lane & 15);                        // + mi*16
    int a_ubase = (lane >> 4);                                // + 2*ks
    int b_row = wn * 32 + ((lane >> 4) << 3) + (lane & 7);    // + nj*16
    int b_ubase = ((lane >> 3) & 1);                          // + 2*ks

    float acc[2][4][4];
    #pragma unroll
    for (int mi = 0; mi < 2; mi++)
        #pragma unroll
        for (int ni = 0; ni < 4; ni++)
            #pragma unroll
            for (int q = 0; q < 4; q++) acc[mi][ni][q] = 0.f;

    load_stage(0, sb,          pos, mt, nt, tid); cp_commit();
    load_stage(1, sb + 24576,  pos, mt, nt, tid); cp_commit();
    load_stage(2, sb + 49152,  pos, mt, nt, tid); cp_commit();

    uint32_t ah[2][2][4];     // [buf][mi][4]
    uint32_t bh[2][4][2];     // [buf][ni][2]

    for (int s = 0; s < 324; s++) {
        cp_wait<2>();                       // stage s resident
        __syncthreads();                    // slot (s+3)&3 free for reuse
        if (s + 3 < 324)
            load_stage(s + 3, sb + ((s + 3) & 3) * 24576, pos, mt, nt, tid);
        cp_commit();

        uint32_t sA = sb + (s & 3) * 24576;
        uint32_t sB = sA + 16384;

        // prime fragments for ks=0
        {
            #pragma unroll
            for (int mi = 0; mi < 2; mi++)
                ldm4(ah[0][mi], sA + swz8(a_row + mi * 16, a_ubase));
            #pragma unroll
            for (int nj = 0; nj < 2; nj++) {
                uint32_t r[4];
                ldm4(r, sB + swz8(b_row + nj * 16, b_ubase));
                bh[0][2 * nj][0] = r[0]; bh[0][2 * nj][1] = r[1];
                bh[0][2 * nj + 1][0] = r[2]; bh[0][2 * nj + 1][1] = r[3];
            }
        }

        #pragma unroll
        for (int ks = 0; ks < 4; ks++) {
            int cur = ks & 1, nxt = cur ^ 1;
            if (ks < 3) {                    // prefetch ks+1 fragments
                int u_a = a_ubase + 2 * (ks + 1);
                int u_b = b_ubase + 2 * (ks + 1);
                #pragma unroll
                for (int mi = 0; mi < 2; mi++)
                    ldm4(ah[nxt][mi], sA + swz8(a_row + mi * 16, u_a));
                #pragma unroll
                for (int nj = 0; nj < 2; nj++) {
                    uint32_t r[4];
                    ldm4(r, sB + swz8(b_row + nj * 16, u_b));
                    bh[nxt][2 * nj][0] = r[0]; bh[nxt][2 * nj][1] = r[1];
                    bh[nxt][2 * nj + 1][0] = r[2]; bh[nxt][2 * nj + 1][1] = r[3];
                }
            }
            #pragma unroll
            for (int mi = 0; mi < 2; mi++)
                #pragma unroll
                for (int ni = 0; ni < 4; ni++)
                    mma16816(acc[mi][ni], ah[cur][mi], bh[cur][ni]);
        }
    }

    // ---- epilogue: bias + squash (butterfly over d = lane>>2) -> g_u ------
    const float inv = 1.f / 4096.f;
    #pragma unroll
    for (int mi = 0; mi < 2; mi++) {
        #pragma unroll
        for (int q = 0; q < 4; q++) {
            int m = mt * 128 + wm * 32 + mi * 16 + ((q >> 1) << 3) + (lane >> 2);
            float bias = pcb[m];
            int i = (m >> 3) * 36 + pos;
            int d = lane >> 2;
            #pragma unroll
            for (int ni = 0; ni < 4; ni++) {
                int n = nt * 64 + wn * 32 + ni * 8 + (lane & 3) * 2 + (q & 1);
                float val = acc[mi][ni][q] * inv + bias;
                float sq = val * val;
                sq += __shfl_xor_sync(0xffffffffu, sq, 4);
                sq += __shfl_xor_sync(0xffffffffu, sq, 8);
                sq += __shfl_xor_sync(0xffffffffu, sq, 16);
                float coef = sq / ((1.f + sq) * sqrtf(sq + 1e-8f));
                g_u[((size_t)i * 256 + n) * 8 + d] = coef * val;
            }
        }
    }
}

// ------------------------------ u_hat (fp16 out) ---------------------------
__global__ void uhat_kernel(const float* __restrict__ W) {
    __shared__ float Ws[8 * JO];
    int i = blockIdx.x, bgrp = blockIdx.y;
    int tid = threadIdx.x;
    for (int e = tid; e < 8 * JO; e += 320) Ws[e] = W[(size_t)i * 1280 + e];
    __syncthreads();
    int t = tid % JO, g = tid / JO;
    for (int bb = 0; bb < 16; bb++) {
        int b = bgrp * 32 + bb * 2 + g;
        const float* up = g_u + ((size_t)i * 256 + b) * 8;
        float a = 0.f;
        #pragma unroll
        for (int dd = 0; dd < 8; dd++) a += up[dd] * Ws[dd * JO + t];
        g_uhat[((size_t)b * NPRI + i) * JO + t] = __float2half_rn(a);
    }
}

// ------------------------------ routing ------------------------------------
__global__ void routing_kernel(float* __restrict__ out) {
    extern __shared__ float sm[];
    float* l    = sm;
    float* cpl  = sm + 11520;
    float* sred = sm + 23040;
    float* v    = sm + 23520;

    int b = blockIdx.x, tid = threadIdx.x;
    for (int e = tid; e < 11520; e += 480) l[e] = 0.f;
    __syncthreads();

    const __half* uh = g_uhat + (size_t)b * NPRI * JO;
    int t = tid % JO, g = tid / JO;
    int j = t >> 4;

    for (int it = 0; it < 3; it++) {
        for (int row = tid; row < NPRI; row += 480) {
            float lv[10]; float m = -1e30f;
            #pragma unroll
            for (int jj = 0; jj < 10; jj++) { lv[jj] = l[row * 10 + jj]; m = fmaxf(m, lv[jj]); }
            float sum = 0.f;
            #pragma unroll
            for (int jj = 0; jj < 10; jj++) { lv[jj] = __expf(lv[jj] - m); sum += lv[jj]; }
            float r = 1.f / sum;
            #pragma unroll
            for (int jj = 0; jj < 10; jj++) cpl[row * 10 + jj] = lv[jj] * r;
        }
        __syncthreads();

        float s0 = 0.f, s1 = 0.f, s2 = 0.f, s3 = 0.f;
        int i0 = g * 384;
        for (int i = i0; i < i0 + 384; i += 4) {
            s0 += cpl[(i + 0) * 10 + j] * __half2float(uh[(size_t)(i + 0) * JO + t]);
            s1 += cpl[(i + 1) * 10 + j] * __half2float(uh[(size_t)(i + 1) * JO + t]);
            s2 += cpl[(i + 2) * 10 + j] * __half2float(uh[(size_t)(i + 2) * JO + t]);
            s3 += cpl[(i + 3) * 10 + j] * __half2float(uh[(size_t)(i + 3) * JO + t]);
        }
        sred[g * JO + t] = (s0 + s1) + (s2 + s3);
        __syncthreads();

        if (tid < JO) {
            float s = sred[t] + sred[JO + t] + sred[2 * JO + t];
            float sq = s * s;
            #pragma unroll
            for (int msk = 8; msk >= 1; msk >>= 1)
                sq += __shfl_xor_sync(0xffffffff, sq, msk);
            float coef = sq / ((1.f + sq) * sqrtf(sq + 1e-8f));
            float vv = coef * s;
            v[t] = vv;
            if (it == 2) out[b * JO + t] = vv;
        }
        __syncthreads();

        if (it < 2) {
            for (int pr = tid; pr < 11520; pr += 480) {
                int i = pr / 10, jj = pr % 10;
                const __half2* up2 = (const __half2*)(uh + (size_t)i * JO + jj * 16);
                const float* vp = v + jj * 16;
                float dot = 0.f;
                #pragma unroll
                for (int o = 0; o < 8; o++) {
                    float2 p2 = __half22float2(up2[o]);
                    dot += p2.x * vp[2 * o] + p2.y * vp[2 * o + 1];
                }
                l[pr] += dot;
            }
            __syncthreads();
        }
    }
}

// ------------------------------ launch -------------------------------------
extern "C" void kernel_launch(void* const* d_in, const int* in_sizes, int n_in,
                              void* d_out, int out_size) {
    const float *x = nullptr, *w1 = nullptr, *b1 = nullptr;
    const float *wp = nullptr, *bp = nullptr, *Wd = nullptr;
    int n256 = 0;
    for (int i = 0; i < n_in; i++) {
        int s = in_sizes[i];
        const float* p = (const float*)d_in[i];
        if      (s == 200704)  x  = p;
        else if (s == 20736)   w1 = p;
        else if (s == 5308416) wp = p;
        else if (s == 1474560) Wd = p;
        else if (s == 256) { if (n256 == 0) b1 = p; else bp = p; n256++; }
    }
    if (!x  && n_in > 0) x  = (const float*)d_in[0];
    if (!w1 && n_in > 1) w1 = (const float*)d_in[1];
    if (!b1 && n_in > 2) b1 = (const float*)d_in[2];
    if (!wp && n_in > 3) wp = (const float*)d_in[3];
    if (!bp && n_in > 4) bp = (const float*)d_in[4];
    if (!Wd && n_in > 5) Wd = (const float*)d_in[5];

    cudaFuncSetAttribute(wsplit_kernel,
                         cudaFuncAttributeMaxDynamicSharedMemorySize, 82944);
    cudaFuncSetAttribute(caps_gemm_kernel,
                         cudaFuncAttributeMaxDynamicSharedMemorySize, 98304);
    cudaFuncSetAttribute(routing_kernel,
                         cudaFuncAttributeMaxDynamicSharedMemorySize, 94720);

    repack_w1_kernel<<<81, 256>>>(w1);
    wsplit_kernel<<<256, 256, 82944>>>(wp);
    conv1_kernel<<<512, 256>>>(x, b1);
    caps_gemm_kernel<<<288, 256, 98304>>>(bp);
    uhat_kernel<<<dim3(1152, 8), 320>>>(Wd);
    routing_kernel<<<256, 480, 94720>>>((float*)d_out);
}

// round 15
// speedup vs baseline: 1.1537x; 1.1537x over previous
#include <cuda_runtime.h>
#include <cuda_fp16.h>
#include <cstdint>

// ---------------------------------------------------------------------------
// CapsuleNetwork forward, GB300 sm_103a — baseline-PTX tensor cores.
// Plain fp16 GEMM, x64 operand scaling (power-of-2, exact).
// R14: caps_gemm reverted to the proven R12 config (128x128, K=128 stages,
//      3-deep ring, 512 thr, fused squash).  Routing rewritten as 3 fused
//      passes over u_hat (was 5): agreement+softmax+s in one warp-per-row pass.
//
// Launches:
//  1. repack_w1 : conv1_w (c,81) -> w1t (81,256)
//  2. wsplit    : pc_w (n,c,81) -> 64*W fp16 [81][outch][c]  (smem-staged)
//  3. conv1     : x -> relu -> 64*h fp16 [pos][b][c]  (fused transpose)
//  4. caps_gemm : mma.sync 128x128, K=128/stage, fused bias+squash -> u
//  5. uhat      : u x W_digit -> u_hat fp16 (B,1152,160)
//  6. routing   : 3 fused routing passes per image -> v
// ---------------------------------------------------------------------------

#define NB    256
#define HW1   400
#define NPRI  1152
#define JO    160

// ------------------------------- scratch -----------------------------------
__device__ float g_w1t[81 * 256];
__device__ __half g_hh[(size_t)400 * 256 * 256];           // 52.4 MB [pos][b][c]
__device__ __half g_wh[(size_t)81 * 256 * 256];            // 10.6 MB [k][n][c]
__device__ float g_u  [(size_t)NPRI * 256 * 8];            // 9.4 MB  [i][b][d]
__device__ __half g_uhat[(size_t)NB * NPRI * JO];          // 94.4 MB

// ------------------------------ ptx helpers --------------------------------
__device__ __forceinline__ uint32_t smem_u32(const void* p) {
    uint32_t a;
    asm("{ .reg .u64 t; cvta.to.shared.u64 t, %1; cvt.u32.u64 %0, t; }"
        : "=r"(a) : "l"(p));
    return a;
}
__device__ __forceinline__ void cpasync16(uint32_t s, const void* g) {
    asm volatile("cp.async.cg.shared.global [%0], [%1], 16;" :: "r"(s), "l"(g));
}
__device__ __forceinline__ void cp_commit() {
    asm volatile("cp.async.commit_group;" ::: "memory");
}
template<int N> __device__ __forceinline__ void cp_wait() {
    asm volatile("cp.async.wait_group %0;" :: "n"(N) : "memory");
}
__device__ __forceinline__ void ldm4(uint32_t* r, uint32_t a) {
    asm volatile("ldmatrix.sync.aligned.m8n8.x4.shared.b16 {%0,%1,%2,%3}, [%4];"
                 : "=r"(r[0]), "=r"(r[1]), "=r"(r[2]), "=r"(r[3]) : "r"(a));
}
__device__ __forceinline__ void mma16816(float* c, const uint32_t* a,
                                         const uint32_t* b) {
    asm volatile(
        "mma.sync.aligned.m16n8k16.row.col.f32.f16.f16.f32 "
        "{%0,%1,%2,%3}, {%4,%5,%6,%7}, {%8,%9}, {%0,%1,%2,%3};"
        : "+f"(c[0]), "+f"(c[1]), "+f"(c[2]), "+f"(c[3])
        : "r"(a[0]), "r"(a[1]), "r"(a[2]), "r"(a[3]), "r"(b[0]), "r"(b[1]));
}

// ------------------------------ f32x2 helpers ------------------------------
__device__ __forceinline__ unsigned long long pk2(float lo, float hi) {
    unsigned long long r;
    asm("mov.b64 %0, {%1, %2};" : "=l"(r) : "f"(lo), "f"(hi));
    return r;
}
__device__ __forceinline__ void upk2(unsigned long long v, float& lo, float& hi) {
    asm("mov.b64 {%0, %1}, %2;" : "=f"(lo), "=f"(hi) : "l"(v));
}
__device__ __forceinline__ void fma2(unsigned long long& d,
                                     unsigned long long a, unsigned long long b) {
    asm("fma.rn.f32x2 %0, %1, %2, %0;" : "+l"(d) : "l"(a), "l"(b));
}

// ------------------------------ repacks ------------------------------------
__global__ void repack_w1_kernel(const float* __restrict__ w) {
    int k = blockIdx.x, c = threadIdx.x;
    g_w1t[k * 256 + c] = w[c * 81 + k];
}

// block = one outch n; smem-staged coalesced load, conflict-free stride-81 read.
__global__ void wsplit_kernel(const float* __restrict__ w) {
    extern __shared__ float wsm[];          // 20736 floats
    int n = blockIdx.x, tid = threadIdx.x;
    const float* src = w + (size_t)n * 20736;
    for (int e = tid; e < 20736; e += 256) wsm[e] = src[e] * 64.f;
    __syncthreads();
    int c = tid;
    for (int k = 0; k < 81; k++) {
        g_wh[((size_t)k * 256 + n) * 256 + c] = __float2half_rn(wsm[c * 81 + k]);
    }
}

// ------------------------------ conv1 (fused fp16 out, NP=5) ---------------
__device__ __forceinline__ void conv1_tile5(const float* __restrict__ ws,
                                            const float* __restrict__ xs,
                                            const float* __restrict__ bias,
                                            int b, int h0, int tx, int ty, int chunk) {
    const int NP = 5;
    int idx[NP], posA[NP];
    #pragma unroll
    for (int p = 0; p < NP; p++) {
        int pos = ty + 16 * (chunk * NP + p);
        posA[p] = pos;
        idx[p] = (pos / 20) * 28 + (pos % 20);
    }
    unsigned long long acc[NP][4];
    #pragma unroll
    for (int p = 0; p < NP; p++)
        #pragma unroll
        for (int q = 0; q < 4; q++) acc[p][q] = 0ull;

    for (int ky = 0; ky < 9; ky++) {
        for (int kx = 0; kx < 9; kx++) {
            int k = ky * 9 + kx;
            float4 wa = ((const float4*)ws)[k * 32 + tx];
            float4 wb = ((const float4*)ws)[k * 32 + 16 + tx];
            unsigned long long w0 = pk2(wa.x, wa.y), w1 = pk2(wa.z, wa.w);
            unsigned long long w2 = pk2(wb.x, wb.y), w3 = pk2(wb.z, wb.w);
            int off = ky * 28 + kx;
            #pragma unroll
            for (int p = 0; p < NP; p++) {
                float xv = xs[idx[p] + off];
                unsigned long long xx = pk2(xv, xv);
                fma2(acc[p][0], w0, xx);
                fma2(acc[p][1], w1, xx);
                fma2(acc[p][2], w2, xx);
                fma2(acc[p][3], w3, xx);
            }
        }
    }
    // store: relu, x64, fp16, layout [pos][b][c]
    #pragma unroll
    for (int p = 0; p < NP; p++) {
        int pos = posA[p];
        #pragma unroll
        for (int q = 0; q < 4; q++) {
            float lo, hi; upk2(acc[p][q], lo, hi);
            int ch = (q < 2) ? (h0 + tx * 4 + 2 * q) : (h0 + 64 + tx * 4 + 2 * (q - 2));
            int bi = 2 * q;
            float v0 = fmaxf(lo + bias[bi], 0.f) * 64.f;
            float v1 = fmaxf(hi + bias[bi + 1], 0.f) * 64.f;
            size_t o = ((size_t)pos * 256 + b) * 256 + ch;
            *(__half2*)(g_hh + o) = __floats2half2_rn(v0, v1);
        }
    }
}

__global__ __launch_bounds__(256, 2)
void conv1_kernel(const float* __restrict__ x, const float* __restrict__ b1) {
    __shared__ float ws[81 * 128];
    __shared__ float xs[784];
    int bx = blockIdx.x;
    int b  = bx >> 1;
    int h0 = (bx & 1) << 7;
    int tid = threadIdx.x;
    {
        float4* wd = (float4*)ws;
        for (int e = tid; e < 81 * 32; e += 256) {
            int k = e >> 5, v = e & 31;
            wd[e] = ((const float4*)g_w1t)[k * 64 + (h0 >> 2) + v];
        }
        float4* xd = (float4*)xs;
        const float4* xsrc = (const float4*)(x + b * 784);
        for (int e = tid; e < 196; e += 256) xd[e] = xsrc[e];
    }
    __syncthreads();
    int tx = tid & 15, ty = tid >> 4;
    float bias[8];
    #pragma unroll
    for (int cc = 0; cc < 4; cc++) {
        bias[cc]     = b1[h0 + tx * 4 + cc];
        bias[4 + cc] = b1[h0 + 64 + tx * 4 + cc];
    }
    #pragma unroll
    for (int chunk = 0; chunk < 5; chunk++)
        conv1_tile5(ws, xs, bias, b, h0, tx, ty, chunk);
}

// ------------------------------ caps_gemm (R12 proven) ---------------------
// grid 144 = 36 pos x 2 mt x 2 nt.  CTA tile M128(outch) x N128(batch).
// K=128/stage (two 32KB substages), 162 stages, 3-deep 64KB ring (192KB).
// 512 threads, 16 warps 4(M)x4(N), warp tile 32x32, fragment double-buffer.
// Epilogue: bias + squash fused via shfl butterfly over d-lanes -> g_u.
__device__ __forceinline__ uint32_t swz8(int row, int u) {
    return (uint32_t)(row * 128 + ((u ^ (row & 7)) * 16));
}

// substage: 32KB = A(16KB) + B(16KB), K=64 (one c-chunk of a koff)
__device__ __forceinline__ void load_sub(int s, uint32_t sbase,
                                         int pos, int mt, int nt, int tid) {
    int koff = s >> 2, c0 = (s & 3) << 6;
    int ky = koff / 9, kx = koff - ky * 9;
    int oy = pos / 6, ox = pos % 6;
    int plin = (2 * oy + ky) * 20 + (2 * ox + kx);
    int row = tid >> 2;
    int u0 = (tid & 3) * 2;
    size_t aoff = ((size_t)(koff * 256 + mt * 128 + row)) * 256 + c0;
    size_t boff = ((size_t)(plin * 256 + nt * 128 + row)) * 256 + c0;
    #pragma unroll
    for (int uu = 0; uu < 2; uu++) {
        int u = u0 + uu;
        uint32_t so = swz8(row, u);
        cpasync16(sbase + so,         g_wh + aoff + u * 8);
        cpasync16(sbase + 16384 + so, g_hh + boff + u * 8);
    }
}

__device__ __forceinline__ void load_big(int sb_idx, uint32_t slot,
                                         int pos, int mt, int nt, int tid) {
    load_sub(2 * sb_idx,     slot,         pos, mt, nt, tid);
    load_sub(2 * sb_idx + 1, slot + 32768, pos, mt, nt, tid);
}

__global__ __launch_bounds__(512, 1)
void caps_gemm_kernel(const float* __restrict__ pcb) {
    extern __shared__ char smem[];
    uint32_t sb = smem_u32(smem);

    int tid = threadIdx.x, lane = tid & 31, wid = tid >> 5;
    int wm = wid >> 2, wn = wid & 3;
    int bid = blockIdx.x;
    int pos = bid >> 2, mt = (bid >> 1) & 1, nt = bid & 1;

    // per-warp static ldmatrix offsets
    int a_row = wm * 32 + (lane & 15);                        // + mi*16
    int a_ubase = (lane >> 4);                                // + 2*ks4
    int b_row = wn * 32 + ((lane >> 4) << 3) + (lane & 7);    // + nj*16
    int b_ubase = ((lane >> 3) & 1);                          // + 2*ks4

    float acc[2][4][4];
    #pragma unroll
    for (int mi = 0; mi < 2; mi++)
        #pragma unroll
        for (int ni = 0; ni < 4; ni++)
            #pragma unroll
            for (int q = 0; q < 4; q++) acc[mi][ni][q] = 0.f;

    load_big(0, sb,          pos, mt, nt, tid); cp_commit();
    load_big(1, sb + 65536,  pos, mt, nt, tid); cp_commit();

    uint32_t ah[2][2][4];     // [buf][mi][4]
    uint32_t bh[2][4][2];     // [buf][ni][2]

    for (int s = 0; s < 162; s++) {
        cp_wait<1>();                       // big stage s resident
        __syncthreads();
        if (s + 2 < 162)
            load_big(s + 2, sb + ((s + 2) % 3) * 65536, pos, mt, nt, tid);
        cp_commit();

        uint32_t slot = sb + (s % 3) * 65536;

        // prime fragments for ks=0 (substage 0)
        {
            #pragma unroll
            for (int mi = 0; mi < 2; mi++)
                ldm4(ah[0][mi], slot + swz8(a_row + mi * 16, a_ubase));
            #pragma unroll
            for (int nj = 0; nj < 2; nj++) {
                uint32_t r[4];
                ldm4(r, slot + 16384 + swz8(b_row + nj * 16, b_ubase));
                bh[0][2 * nj][0] = r[0]; bh[0][2 * nj][1] = r[1];
                bh[0][2 * nj + 1][0] = r[2]; bh[0][2 * nj + 1][1] = r[3];
            }
        }

        #pragma unroll
        for (int ks = 0; ks < 8; ks++) {
            int cur = ks & 1, nxt = cur ^ 1;
            if (ks < 7) {                    // prefetch ks+1 fragments
                int ksn = ks + 1;
                uint32_t sA = slot + (ksn >> 2) * 32768;
                uint32_t sB = sA + 16384;
                int u_a = a_ubase + 2 * (ksn & 3);
                int u_b = b_ubase + 2 * (ksn & 3);
                #pragma unroll
                for (int mi = 0; mi < 2; mi++)
                    ldm4(ah[nxt][mi], sA + swz8(a_row + mi * 16, u_a));
                #pragma unroll
                for (int nj = 0; nj < 2; nj++) {
                    uint32_t r[4];
                    ldm4(r, sB + swz8(b_row + nj * 16, u_b));
                    bh[nxt][2 * nj][0] = r[0]; bh[nxt][2 * nj][1] = r[1];
                    bh[nxt][2 * nj + 1][0] = r[2]; bh[nxt][2 * nj + 1][1] = r[3];
                }
            }
            #pragma unroll
            for (int mi = 0; mi < 2; mi++)
                #pragma unroll
                for (int ni = 0; ni < 4; ni++)
                    mma16816(acc[mi][ni], ah[cur][mi], bh[cur][ni]);
        }
    }

    // ---- epilogue: bias + squash (butterfly over d = lane>>2) -> g_u ------
    const float inv = 1.f / 4096.f;
    #pragma unroll
    for (int mi = 0; mi < 2; mi++) {
        #pragma unroll
        for (int q = 0; q < 4; q++) {
            int m = mt * 128 + wm * 32 + mi * 16 + ((q >> 1) << 3) + (lane >> 2);
            float bias = pcb[m];
            int i = (m >> 3) * 36 + pos;
            int d = lane >> 2;
            #pragma unroll
            for (int ni = 0; ni < 4; ni++) {
                int n = nt * 128 + wn * 32 + ni * 8 + (lane & 3) * 2 + (q & 1);
                float val = acc[mi][ni][q] * inv + bias;
                float sq = val * val;
                sq += __shfl_xor_sync(0xffffffffu, sq, 4);
                sq += __shfl_xor_sync(0xffffffffu, sq, 8);
                sq += __shfl_xor_sync(0xffffffffu, sq, 16);
                float coef = sq / ((1.f + sq) * sqrtf(sq + 1e-8f));
                g_u[((size_t)i * 256 + n) * 8 + d] = coef * val;
            }
        }
    }
}

// ------------------------------ u_hat (fp16 out) ---------------------------
__global__ void uhat_kernel(const float* __restrict__ W) {
    __shared__ float Ws[8 * JO];
    int i = blockIdx.x, bgrp = blockIdx.y;
    int tid = threadIdx.x;
    for (int e = tid; e < 8 * JO; e += 320) Ws[e] = W[(size_t)i * 1280 + e];
    __syncthreads();
    int t = tid % JO, g = tid / JO;
    for (int bb = 0; bb < 16; bb++) {
        int b = bgrp * 32 + bb * 2 + g;
        const float* up = g_u + ((size_t)i * 256 + b) * 8;
        float a = 0.f;
        #pragma unroll
        for (int dd = 0; dd < 8; dd++) a += up[dd] * Ws[dd * JO + t];
        g_uhat[((size_t)b * NPRI + i) * JO + t] = __float2half_rn(a);
    }
}

// ------------------------------ routing (fused 3-pass) ---------------------
// block = one image, 384 thr = 12 warps.  Warp-per-row fused pass:
// dot(agreement) -> logit update -> softmax -> s contribution, one u_hat read.
// u_hat passes: it0 (uniform c) + it1 + it2  = 3 (was 5).
// smem: l[11520] + sred[12*160] + v[160] = 54400 B
__global__ __launch_bounds__(384, 2)
void routing_kernel(float* __restrict__ out) {
    extern __shared__ float sm[];
    float* l    = sm;              // 11520
    float* sred = sm + 11520;      // 1920
    float* v    = sm + 13440;      // 160

    int b = blockIdx.x, tid = threadIdx.x;
    int lane = tid & 31, w = tid >> 5;      // 12 warps
    const __half* uh = g_uhat + (size_t)b * NPRI * JO;

    // ---- pass 0: c = 0.1 uniform -----------------------------------------
    {
        float sp[5] = {0.f, 0.f, 0.f, 0.f, 0.f};
        for (int i = w; i < NPRI; i += 12) {
            const __half* row = uh + (size_t)i * JO;
            #pragma unroll
            for (int k = 0; k < 5; k++) sp[k] += __half2float(row[lane + 32 * k]);
        }
        #pragma unroll
        for (int k = 0; k < 5; k++) sred[w * 160 + lane + 32 * k] = sp[k];
    }
    __syncthreads();
    if (tid < 160) {
        float s = 0.f;
        #pragma unroll
        for (int ww = 0; ww < 12; ww++) s += sred[ww * 160 + tid];
        s *= 0.1f;
        float sq = s * s;
        #pragma unroll
        for (int m = 8; m >= 1; m >>= 1) sq += __shfl_xor_sync(0xffffffffu, sq, m);
        float coef = sq / ((1.f + sq) * sqrtf(sq + 1e-8f));
        v[tid] = coef * s;
    }
    __syncthreads();

    // ---- passes 1,2: fused agreement + softmax + s ------------------------
    for (int it = 1; it < 3; it++) {
        float vt[5];
        #pragma unroll
        for (int k = 0; k < 5; k++) vt[k] = v[lane + 32 * k];
        int jb = lane >> 4;                       // 0 or 1 (j parity base)
        float sp[5] = {0.f, 0.f, 0.f, 0.f, 0.f};

        for (int i = w; i < NPRI; i += 12) {
            const __half* row = uh + (size_t)i * JO;
            float u[5], d[5];
            #pragma unroll
            for (int k = 0; k < 5; k++) {
                u[k] = __half2float(row[lane + 32 * k]);
                d[k] = u[k] * vt[k];
            }
            // reduce over o (16-lane groups share j)
            #pragma unroll
            for (int m = 1; m < 16; m <<= 1) {
                #pragma unroll
                for (int k = 0; k < 5; k++)
                    d[k] += __shfl_xor_sync(0xffffffffu, d[k], m);
            }
            // d[k] = dot for j = jb + 2k
            float lnew[5];
            if (it == 1) {
                #pragma unroll
                for (int k = 0; k < 5; k++) lnew[k] = d[k];
                if ((lane & 15) == 0) {
                    #pragma unroll
                    for (int k = 0; k < 5; k++) l[i * 10 + jb + 2 * k] = d[k];
                }
            } else {
                #pragma unroll
                for (int k = 0; k < 5; k++) lnew[k] = l[i * 10 + jb + 2 * k] + d[k];
            }
            // softmax over 10 j (5 own + 5 from partner half)
            float m5 = lnew[0];
            #pragma unroll
            for (int k = 1; k < 5; k++) m5 = fmaxf(m5, lnew[k]);
            float mm = fmaxf(m5, __shfl_xor_sync(0xffffffffu, m5, 16));
            float e[5]; float se = 0.f;
            #pragma unroll
            for (int k = 0; k < 5; k++) { e[k] = __expf(lnew[k] - mm); se += e[k]; }
            se += __shfl_xor_sync(0xffffffffu, se, 16);
            float r = 1.f / se;
            #pragma unroll
            for (int k = 0; k < 5; k++) sp[k] += e[k] * r * u[k];
        }
        #pragma unroll
        for (int k = 0; k < 5; k++) sred[w * 160 + lane + 32 * k] = sp[k];
        __syncthreads();

        if (tid < 160) {
            float s = 0.f;
            #pragma unroll
            for (int ww = 0; ww < 12; ww++) s += sred[ww * 160 + tid];
            float sq = s * s;
            #pragma unroll
            for (int m = 8; m >= 1; m >>= 1) sq += __shfl_xor_sync(0xffffffffu, sq, m);
            float coef = sq / ((1.f + sq) * sqrtf(sq + 1e-8f));
            float vv = coef * s;
            v[tid] = vv;
            if (it == 2) out[b * JO + tid] = vv;
        }
        __syncthreads();
    }
}

// ------------------------------ launch -------------------------------------
extern "C" void kernel_launch(void* const* d_in, const int* in_sizes, int n_in,
                              void* d_out, int out_size) {
    const float *x = nullptr, *w1 = nullptr, *b1 = nullptr;
    const float *wp = nullptr, *bp = nullptr, *Wd = nullptr;
    int n256 = 0;
    for (int i = 0; i < n_in; i++) {
        int s = in_sizes[i];
        const float* p = (const float*)d_in[i];
        if      (s == 200704)  x  = p;
        else if (s == 20736)   w1 = p;
        else if (s == 5308416) wp = p;
        else if (s == 1474560) Wd = p;
        else if (s == 256) { if (n256 == 0) b1 = p; else bp = p; n256++; }
    }
    if (!x  && n_in > 0) x  = (const float*)d_in[0];
    if (!w1 && n_in > 1) w1 = (const float*)d_in[1];
    if (!b1 && n_in > 2) b1 = (const float*)d_in[2];
    if (!wp && n_in > 3) wp = (const float*)d_in[3];
    if (!bp && n_in > 4) bp = (const float*)d_in[4];
    if (!Wd && n_in > 5) Wd = (const float*)d_in[5];

    cudaFuncSetAttribute(wsplit_kernel,
                         cudaFuncAttributeMaxDynamicSharedMemorySize, 82944);
    cudaFuncSetAttribute(caps_gemm_kernel,
                         cudaFuncAttributeMaxDynamicSharedMemorySize, 196608);
    cudaFuncSetAttribute(routing_kernel,
                         cudaFuncAttributeMaxDynamicSharedMemorySize, 54400);

    repack_w1_kernel<<<81, 256>>>(w1);
    wsplit_kernel<<<256, 256, 82944>>>(wp);
    conv1_kernel<<<512, 256>>>(x, b1);
    caps_gemm_kernel<<<144, 512, 196608>>>(bp);
    uhat_kernel<<<dim3(1152, 8), 320>>>(Wd);
    routing_kernel<<<256, 384, 54400>>>((float*)d_out);
}

// round 16
// speedup vs baseline: 1.1649x; 1.0096x over previous
#include <cuda_runtime.h>
#include <cuda_fp16.h>
#include <cstdint>

// ---------------------------------------------------------------------------
// CapsuleNetwork forward, GB300 sm_103a — baseline-PTX tensor cores.
// Plain fp16 GEMM, x64 operand scaling (power-of-2, exact).
// R16 = R12 (best known) + conv1 smem-staged coalesced stores.
//
// Launches:
//  1. repack_w1 : conv1_w (c,81) -> w1t (81,256)
//  2. wsplit    : pc_w (n,c,81) -> 64*W fp16 [81][outch][c]  (smem-staged)
//  3. conv1     : x -> relu -> 64*h fp16 [pos][b][c]  (staged coalesced out)
//  4. caps_gemm : mma.sync 128x128, K=128/stage, fused bias+squash -> u
//  5. uhat      : u x W_digit -> u_hat fp16 (B,1152,160)
//  6. routing   : 3 routing iters fused per image -> v  (R12 version)
// ---------------------------------------------------------------------------

#define NB    256
#define HW1   400
#define NPRI  1152
#define JO    160

// ------------------------------- scratch -----------------------------------
__device__ float g_w1t[81 * 256];
__device__ __half g_hh[(size_t)400 * 256 * 256];           // 52.4 MB [pos][b][c]
__device__ __half g_wh[(size_t)81 * 256 * 256];            // 10.6 MB [k][n][c]
__device__ float g_u  [(size_t)NPRI * 256 * 8];            // 9.4 MB  [i][b][d]
__device__ __half g_uhat[(size_t)NB * NPRI * JO];          // 94.4 MB

// ------------------------------ ptx helpers --------------------------------
__device__ __forceinline__ uint32_t smem_u32(const void* p) {
    uint32_t a;
    asm("{ .reg .u64 t; cvta.to.shared.u64 t, %1; cvt.u32.u64 %0, t; }"
        : "=r"(a) : "l"(p));
    return a;
}
__device__ __forceinline__ void cpasync16(uint32_t s, const void* g) {
    asm volatile("cp.async.cg.shared.global [%0], [%1], 16;" :: "r"(s), "l"(g));
}
__device__ __forceinline__ void cp_commit() {
    asm volatile("cp.async.commit_group;" ::: "memory");
}
template<int N> __device__ __forceinline__ void cp_wait() {
    asm volatile("cp.async.wait_group %0;" :: "n"(N) : "memory");
}
__device__ __forceinline__ void ldm4(uint32_t* r, uint32_t a) {
    asm volatile("ldmatrix.sync.aligned.m8n8.x4.shared.b16 {%0,%1,%2,%3}, [%4];"
                 : "=r"(r[0]), "=r"(r[1]), "=r"(r[2]), "=r"(r[3]) : "r"(a));
}
__device__ __forceinline__ void mma16816(float* c, const uint32_t* a,
                                         const uint32_t* b) {
    asm volatile(
        "mma.sync.aligned.m16n8k16.row.col.f32.f16.f16.f32 "
        "{%0,%1,%2,%3}, {%4,%5,%6,%7}, {%8,%9}, {%0,%1,%2,%3};"
        : "+f"(c[0]), "+f"(c[1]), "+f"(c[2]), "+f"(c[3])
        : "r"(a[0]), "r"(a[1]), "r"(a[2]), "r"(a[3]), "r"(b[0]), "r"(b[1]));
}

// ------------------------------ f32x2 helpers ------------------------------
__device__ __forceinline__ unsigned long long pk2(float lo, float hi) {
    unsigned long long r;
    asm("mov.b64 %0, {%1, %2};" : "=l"(r) : "f"(lo), "f"(hi));
    return r;
}
__device__ __forceinline__ void upk2(unsigned long long v, float& lo, float& hi) {
    asm("mov.b64 {%0, %1}, %2;" : "=f"(lo), "=f"(hi) : "l"(v));
}
__device__ __forceinline__ void fma2(unsigned long long& d,
                                     unsigned long long a, unsigned long long b) {
    asm("fma.rn.f32x2 %0, %1, %2, %0;" : "+l"(d) : "l"(a), "l"(b));
}

// ------------------------------ repacks ------------------------------------
__global__ void repack_w1_kernel(const float* __restrict__ w) {
    int k = blockIdx.x, c = threadIdx.x;
    g_w1t[k * 256 + c] = w[c * 81 + k];
}

// block = one outch n; smem-staged coalesced load, conflict-free stride-81 read.
__global__ void wsplit_kernel(const float* __restrict__ w) {
    extern __shared__ float wsm[];          // 20736 floats
    int n = blockIdx.x, tid = threadIdx.x;
    const float* src = w + (size_t)n * 20736;
    for (int e = tid; e < 20736; e += 256) wsm[e] = src[e] * 64.f;
    __syncthreads();
    int c = tid;
    for (int k = 0; k < 81; k++) {
        g_wh[((size_t)k * 256 + n) * 256 + c] = __float2half_rn(wsm[c * 81 + k]);
    }
}

// ------------------------------ conv1 (staged coalesced stores) ------------
// staging row = 128 fp16 (256B) + 16B pad = 272B
__device__ __forceinline__ void conv1_tile5(const float* __restrict__ ws,
                                            const float* __restrict__ xs,
                                            const float* __restrict__ bias,
                                            char* __restrict__ hs,
                                            int tx, int ty, int chunk) {
    const int NP = 5;
    int idx[NP];
    #pragma unroll
    for (int p = 0; p < NP; p++) {
        int pos = ty + 16 * (chunk * NP + p);
        idx[p] = (pos / 20) * 28 + (pos % 20);
    }
    unsigned long long acc[NP][4];
    #pragma unroll
    for (int p = 0; p < NP; p++)
        #pragma unroll
        for (int q = 0; q < 4; q++) acc[p][q] = 0ull;

    for (int ky = 0; ky < 9; ky++) {
        for (int kx = 0; kx < 9; kx++) {
            int k = ky * 9 + kx;
            float4 wa = ((const float4*)ws)[k * 32 + tx];
            float4 wb = ((const float4*)ws)[k * 32 + 16 + tx];
            unsigned long long w0 = pk2(wa.x, wa.y), w1 = pk2(wa.z, wa.w);
            unsigned long long w2 = pk2(wb.x, wb.y), w3 = pk2(wb.z, wb.w);
            int off = ky * 28 + kx;
            #pragma unroll
            for (int p = 0; p < NP; p++) {
                float xv = xs[idx[p] + off];
                unsigned long long xx = pk2(xv, xv);
                fma2(acc[p][0], w0, xx);
                fma2(acc[p][1], w1, xx);
                fma2(acc[p][2], w2, xx);
                fma2(acc[p][3], w3, xx);
            }
        }
    }
    // store: relu, x64, fp16 -> smem staging [r 0..79][ch 0..127]
    #pragma unroll
    for (int p = 0; p < NP; p++) {
        int r = ty + 16 * p;
        char* rowp = hs + r * 272;
        #pragma unroll
        for (int q = 0; q < 4; q++) {
            float lo, hi; upk2(acc[p][q], lo, hi);
            int bi = 2 * q;
            float v0 = fmaxf(lo + bias[bi], 0.f) * 64.f;
            float v1 = fmaxf(hi + bias[bi + 1], 0.f) * 64.f;
            int off = (q < 2) ? (tx * 8 + q * 4) : (128 + tx * 8 + (q - 2) * 4);
            *(__half2*)(rowp + off) = __floats2half2_rn(v0, v1);
        }
    }
}

__global__ __launch_bounds__(256, 2)
void conv1_kernel(const float* __restrict__ x, const float* __restrict__ b1) {
    extern __shared__ char csm[];
    float* ws = (float*)csm;                 // 41472 B
    float* xs = (float*)(csm + 41472);       // 3136 B
    char*  hs = csm + 44608;                 // 80 * 272 = 21760 B

    int bx = blockIdx.x;
    int b  = bx >> 1;
    int h0 = (bx & 1) << 7;
    int tid = threadIdx.x;
    {
        float4* wd = (float4*)ws;
        for (int e = tid; e < 81 * 32; e += 256) {
            int k = e >> 5, v = e & 31;
            wd[e] = ((const float4*)g_w1t)[k * 64 + (h0 >> 2) + v];
        }
        float4* xd = (float4*)xs;
        const float4* xsrc = (const float4*)(x + b * 784);
        for (int e = tid; e < 196; e += 256) xd[e] = xsrc[e];
    }
    __syncthreads();
    int tx = tid & 15, ty = tid >> 4;
    float bias[8];
    #pragma unroll
    for (int cc = 0; cc < 4; cc++) {
        bias[cc]     = b1[h0 + tx * 4 + cc];
        bias[4 + cc] = b1[h0 + 64 + tx * 4 + cc];
    }
    for (int chunk = 0; chunk < 5; chunk++) {
        conv1_tile5(ws, xs, bias, hs, tx, ty, chunk);
        __syncthreads();
        // coalesced copy-out: 80 rows x 256B
        for (int e = tid; e < 1280; e += 256) {
            int row = e >> 4, seg = e & 15;
            int pos = chunk * 80 + row;
            uint4 v = *(const uint4*)(hs + row * 272 + seg * 16);
            *(uint4*)(g_hh + ((size_t)pos * 256 + b) * 256 + h0 + seg * 8) = v;
        }
        __syncthreads();
    }
}

// ------------------------------ caps_gemm (R12 proven) ---------------------
// grid 144 = 36 pos x 2 mt x 2 nt.  CTA tile M128(outch) x N128(batch).
// K=128/stage (two 32KB substages), 162 stages, 3-deep 64KB ring (192KB).
// 512 threads, 16 warps 4(M)x4(N), warp tile 32x32, fragment double-buffer.
// Epilogue: bias + squash fused via shfl butterfly over d-lanes -> g_u.
__device__ __forceinline__ uint32_t swz8(int row, int u) {
    return (uint32_t)(row * 128 + ((u ^ (row & 7)) * 16));
}

// substage: 32KB = A(16KB) + B(16KB), K=64 (one c-chunk of a koff)
__device__ __forceinline__ void load_sub(int s, uint32_t sbase,
                                         int pos, int mt, int nt, int tid) {
    int koff = s >> 2, c0 = (s & 3) << 6;
    int ky = koff / 9, kx = koff - ky * 9;
    int oy = pos / 6, ox = pos % 6;
    int plin = (2 * oy + ky) * 20 + (2 * ox + kx);
    int row = tid >> 2;
    int u0 = (tid & 3) * 2;
    size_t aoff = ((size_t)(koff * 256 + mt * 128 + row)) * 256 + c0;
    size_t boff = ((size_t)(plin * 256 + nt * 128 + row)) * 256 + c0;
    #pragma unroll
    for (int uu = 0; uu < 2; uu++) {
        int u = u0 + uu;
        uint32_t so = swz8(row, u);
        cpasync16(sbase + so,         g_wh + aoff + u * 8);
        cpasync16(sbase + 16384 + so, g_hh + boff + u * 8);
    }
}

__device__ __forceinline__ void load_big(int sb_idx, uint32_t slot,
                                         int pos, int mt, int nt, int tid) {
    load_sub(2 * sb_idx,     slot,         pos, mt, nt, tid);
    load_sub(2 * sb_idx + 1, slot + 32768, pos, mt, nt, tid);
}

__global__ __launch_bounds__(512, 1)
void caps_gemm_kernel(const float* __restrict__ pcb) {
    extern __shared__ char smem[];
    uint32_t sb = smem_u32(smem);

    int tid = threadIdx.x, lane = tid & 31, wid = tid >> 5;
    int wm = wid >> 2, wn = wid & 3;
    int bid = blockIdx.x;
    int pos = bid >> 2, mt = (bid >> 1) & 1, nt = bid & 1;

    // per-warp static ldmatrix offsets
    int a_row = wm * 32 + (lane & 15);                        // + mi*16
    int a_ubase = (lane >> 4);                                // + 2*ks4
    int b_row = wn * 32 + ((lane >> 4) << 3) + (lane & 7);    // + nj*16
    int b_ubase = ((lane >> 3) & 1);                          // + 2*ks4

    float acc[2][4][4];
    #pragma unroll
    for (int mi = 0; mi < 2; mi++)
        #pragma unroll
        for (int ni = 0; ni < 4; ni++)
            #pragma unroll
            for (int q = 0; q < 4; q++) acc[mi][ni][q] = 0.f;

    load_big(0, sb,          pos, mt, nt, tid); cp_commit();
    load_big(1, sb + 65536,  pos, mt, nt, tid); cp_commit();

    uint32_t ah[2][2][4];     // [buf][mi][4]
    uint32_t bh[2][4][2];     // [buf][ni][2]

    for (int s = 0; s < 162; s++) {
        cp_wait<1>();                       // big stage s resident
        __syncthreads();
        if (s + 2 < 162)
            load_big(s + 2, sb + ((s + 2) % 3) * 65536, pos, mt, nt, tid);
        cp_commit();

        uint32_t slot = sb + (s % 3) * 65536;

        // prime fragments for ks=0 (substage 0)
        {
            #pragma unroll
            for (int mi = 0; mi < 2; mi++)
                ldm4(ah[0][mi], slot + swz8(a_row + mi * 16, a_ubase));
            #pragma unroll
            for (int nj = 0; nj < 2; nj++) {
                uint32_t r[4];
                ldm4(r, slot + 16384 + swz8(b_row + nj * 16, b_ubase));
                bh[0][2 * nj][0] = r[0]; bh[0][2 * nj][1] = r[1];
                bh[0][2 * nj + 1][0] = r[2]; bh[0][2 * nj + 1][1] = r[3];
            }
        }

        #pragma unroll
        for (int ks = 0; ks < 8; ks++) {
            int cur = ks & 1, nxt = cur ^ 1;
            if (ks < 7) {                    // prefetch ks+1 fragments
                int ksn = ks + 1;
                uint32_t sA = slot + (ksn >> 2) * 32768;
                uint32_t sB = sA + 16384;
                int u_a = a_ubase + 2 * (ksn & 3);
                int u_b = b_ubase + 2 * (ksn & 3);
                #pragma unroll
                for (int mi = 0; mi < 2; mi++)
                    ldm4(ah[nxt][mi], sA + swz8(a_row + mi * 16, u_a));
                #pragma unroll
                for (int nj = 0; nj < 2; nj++) {
                    uint32_t r[4];
                    ldm4(r, sB + swz8(b_row + nj * 16, u_b));
                    bh[nxt][2 * nj][0] = r[0]; bh[nxt][2 * nj][1] = r[1];
                    bh[nxt][2 * nj + 1][0] = r[2]; bh[nxt][2 * nj + 1][1] = r[3];
                }
            }
            #pragma unroll
            for (int mi = 0; mi < 2; mi++)
                #pragma unroll
                for (int ni = 0; ni < 4; ni++)
                    mma16816(acc[mi][ni], ah[cur][mi], bh[cur][ni]);
        }
    }

    // ---- epilogue: bias + squash (butterfly over d = lane>>2) -> g_u ------
    const float inv = 1.f / 4096.f;
    #pragma unroll
    for (int mi = 0; mi < 2; mi++) {
        #pragma unroll
        for (int q = 0; q < 4; q++) {
            int m = mt * 128 + wm * 32 + mi * 16 + ((q >> 1) << 3) + (lane >> 2);
            float bias = pcb[m];
            int i = (m >> 3) * 36 + pos;
            int d = lane >> 2;
            #pragma unroll
            for (int ni = 0; ni < 4; ni++) {
                int n = nt * 128 + wn * 32 + ni * 8 + (lane & 3) * 2 + (q & 1);
                float val = acc[mi][ni][q] * inv + bias;
                float sq = val * val;
                sq += __shfl_xor_sync(0xffffffffu, sq, 4);
                sq += __shfl_xor_sync(0xffffffffu, sq, 8);
                sq += __shfl_xor_sync(0xffffffffu, sq, 16);
                float coef = sq / ((1.f + sq) * sqrtf(sq + 1e-8f));
                g_u[((size_t)i * 256 + n) * 8 + d] = coef * val;
            }
        }
    }
}

// ------------------------------ u_hat (fp16 out) ---------------------------
__global__ void uhat_kernel(const float* __restrict__ W) {
    __shared__ float Ws[8 * JO];
    int i = blockIdx.x, bgrp = blockIdx.y;
    int tid = threadIdx.x;
    for (int e = tid; e < 8 * JO; e += 320) Ws[e] = W[(size_t)i * 1280 + e];
    __syncthreads();
    int t = tid % JO, g = tid / JO;
    for (int bb = 0; bb < 16; bb++) {
        int b = bgrp * 32 + bb * 2 + g;
        const float* up = g_u + ((size_t)i * 256 + b) * 8;
        float a = 0.f;
        #pragma unroll
        for (int dd = 0; dd < 8; dd++) a += up[dd] * Ws[dd * JO + t];
        g_uhat[((size_t)b * NPRI + i) * JO + t] = __float2half_rn(a);
    }
}

// ------------------------------ routing (R12 proven) -----------------------
__global__ void routing_kernel(float* __restrict__ out) {
    extern __shared__ float sm[];
    float* l    = sm;
    float* cpl  = sm + 11520;
    float* sred = sm + 23040;
    float* v    = sm + 23520;

    int b = blockIdx.x, tid = threadIdx.x;
    for (int e = tid; e < 11520; e += 480) l[e] = 0.f;
    __syncthreads();

    const __half* uh = g_uhat + (size_t)b * NPRI * JO;
    int t = tid % JO, g = tid / JO;
    int j = t >> 4;

    for (int it = 0; it < 3; it++) {
        for (int row = tid; row < NPRI; row += 480) {
            float lv[10]; float m = -1e30f;
            #pragma unroll
            for (int jj = 0; jj < 10; jj++) { lv[jj] = l[row * 10 + jj]; m = fmaxf(m, lv[jj]); }
            float sum = 0.f;
            #pragma unroll
            for (int jj = 0; jj < 10; jj++) { lv[jj] = __expf(lv[jj] - m); sum += lv[jj]; }
            float r = 1.f / sum;
            #pragma unroll
            for (int jj = 0; jj < 10; jj++) cpl[row * 10 + jj] = lv[jj] * r;
        }
        __syncthreads();

        float s0 = 0.f, s1 = 0.f, s2 = 0.f, s3 = 0.f;
        int i0 = g * 384;
        for (int i = i0; i < i0 + 384; i += 4) {
            s0 += cpl[(i + 0) * 10 + j] * __half2float(uh[(size_t)(i + 0) * JO + t]);
            s1 += cpl[(i + 1) * 10 + j] * __half2float(uh[(size_t)(i + 1) * JO + t]);
            s2 += cpl[(i + 2) * 10 + j] * __half2float(uh[(size_t)(i + 2) * JO + t]);
            s3 += cpl[(i + 3) * 10 + j] * __half2float(uh[(size_t)(i + 3) * JO + t]);
        }
        sred[g * JO + t] = (s0 + s1) + (s2 + s3);
        __syncthreads();

        if (tid < JO) {
            float s = sred[t] + sred[JO + t] + sred[2 * JO + t];
            float sq = s * s;
            #pragma unroll
            for (int msk = 8; msk >= 1; msk >>= 1)
                sq += __shfl_xor_sync(0xffffffff, sq, msk);
            float coef = sq / ((1.f + sq) * sqrtf(sq + 1e-8f));
            float vv = coef * s;
            v[t] = vv;
            if (it == 2) out[b * JO + t] = vv;
        }
        __syncthreads();

        if (it < 2) {
            for (int pr = tid; pr < 11520; pr += 480) {
                int i = pr / 10, jj = pr % 10;
                const __half2* up2 = (const __half2*)(uh + (size_t)i * JO + jj * 16);
                const float* vp = v + jj * 16;
                float dot = 0.f;
                #pragma unroll
                for (int o = 0; o < 8; o++) {
                    float2 p2 = __half22float2(up2[o]);
                    dot += p2.x * vp[2 * o] + p2.y * vp[2 * o + 1];
                }
                l[pr] += dot;
            }
            __syncthreads();
        }
    }
}

// ------------------------------ launch -------------------------------------
extern "C" void kernel_launch(void* const* d_in, const int* in_sizes, int n_in,
                              void* d_out, int out_size) {
    const float *x = nullptr, *w1 = nullptr, *b1 = nullptr;
    const float *wp = nullptr, *bp = nullptr, *Wd = nullptr;
    int n256 = 0;
    for (int i = 0; i < n_in; i++) {
        int s = in_sizes[i];
        const float* p = (const float*)d_in[i];
        if      (s == 200704)  x  = p;
        else if (s == 20736)   w1 = p;
        else if (s == 5308416) wp = p;
        else if (s == 1474560) Wd = p;
        else if (s == 256) { if (n256 == 0) b1 = p; else bp = p; n256++; }
    }
    if (!x  && n_in > 0) x  = (const float*)d_in[0];
    if (!w1 && n_in > 1) w1 = (const float*)d_in[1];
    if (!b1 && n_in > 2) b1 = (const float*)d_in[2];
    if (!wp && n_in > 3) wp = (const float*)d_in[3];
    if (!bp && n_in > 4) bp = (const float*)d_in[4];
    if (!Wd && n_in > 5) Wd = (const float*)d_in[5];

    cudaFuncSetAttribute(wsplit_kernel,
                         cudaFuncAttributeMaxDynamicSharedMemorySize, 82944);
    cudaFuncSetAttribute(conv1_kernel,
                         cudaFuncAttributeMaxDynamicSharedMemorySize, 66368);
    cudaFuncSetAttribute(caps_gemm_kernel,
                         cudaFuncAttributeMaxDynamicSharedMemorySize, 196608);
    cudaFuncSetAttribute(routing_kernel,
                         cudaFuncAttributeMaxDynamicSharedMemorySize, 94720);

    repack_w1_kernel<<<81, 256>>>(w1);
    wsplit_kernel<<<256, 256, 82944>>>(wp);
    conv1_kernel<<<512, 256, 66368>>>(x, b1);
    caps_gemm_kernel<<<144, 512, 196608>>>(bp);
    uhat_kernel<<<dim3(1152, 8), 320>>>(Wd);
    routing_kernel<<<256, 480, 94720>>>((float*)d_out);
}